// round 1
// baseline (speedup 1.0000x reference)
#include <cuda_runtime.h>
#include <math.h>
#include <stddef.h>

// Problem constants
#define Bsz 64
#define Ns  197
#define Dm  768
#define Hh  12
#define HDh 64
#define DFFc 3072
#define Mrows (Bsz*Ns)          // 12608, divisible by 64

// ---------------------------------------------------------------------------
// Scratch (device globals: no allocations allowed)
// ---------------------------------------------------------------------------
__device__ float g_h  [Mrows*Dm];   // LN1 output, reused for LN2 output
__device__ float g_q  [Mrows*Dm];
__device__ float g_k  [Mrows*Dm];
__device__ float g_v  [Mrows*Dm];
__device__ float g_hs [Mrows*Dm];   // residual after attention block
__device__ float g_ffn[Mrows*DFFc]; // gelu(h2@w1+b1)

// ---------------------------------------------------------------------------
// LayerNorm: one CTA (256 threads) per row of 768
// ---------------------------------------------------------------------------
__global__ void ln_kernel(const float* __restrict__ x,
                          const float* __restrict__ g,
                          const float* __restrict__ b,
                          float* __restrict__ out) {
    int row = blockIdx.x;
    const float* xr = x + (size_t)row * Dm;
    float s = 0.f, s2 = 0.f;
    for (int i = threadIdx.x; i < Dm; i += 256) {
        float v = xr[i];
        s += v; s2 += v * v;
    }
    __shared__ float r1[256], r2[256];
    r1[threadIdx.x] = s; r2[threadIdx.x] = s2;
    __syncthreads();
    #pragma unroll
    for (int o = 128; o > 0; o >>= 1) {
        if (threadIdx.x < o) {
            r1[threadIdx.x] += r1[threadIdx.x + o];
            r2[threadIdx.x] += r2[threadIdx.x + o];
        }
        __syncthreads();
    }
    float mu  = r1[0] * (1.0f / Dm);
    float var = r2[0] * (1.0f / Dm) - mu * mu;
    float inv = rsqrtf(var + 1e-5f);
    float* orow = out + (size_t)row * Dm;
    for (int i = threadIdx.x; i < Dm; i += 256)
        orow[i] = (xr[i] - mu) * inv * g[i] + b[i];
}

// ---------------------------------------------------------------------------
// SGEMM: C = act( (A@B + bias) * alpha + (RESID ? R : 0) )
// Tile 64x64, BK=16, 256 threads, 4x4 per thread.
// All of M, N divisible by 64; K divisible by 16 (768 / 3072).
// ---------------------------------------------------------------------------
template<bool RESID, bool GELU>
__global__ void sgemm_kernel(const float* __restrict__ A,
                             const float* __restrict__ B,
                             const float* __restrict__ bias,
                             const float* __restrict__ R,
                             float* __restrict__ C,
                             int M, int N, int K, float alpha) {
    __shared__ float As[64][17];
    __shared__ float Bs[16][64];

    int tid = threadIdx.x;
    int tx = tid & 15, ty = tid >> 4;
    int row0 = blockIdx.y * 64, col0 = blockIdx.x * 64;

    int ar = tid >> 2, ac = (tid & 3) * 4;   // A tile load coords
    int br = tid >> 4, bc = (tid & 15) * 4;  // B tile load coords

    float acc[4][4] = {};

    for (int kt = 0; kt < K; kt += 16) {
        float4 a4 = *(const float4*)(A + (size_t)(row0 + ar) * K + kt + ac);
        As[ar][ac + 0] = a4.x; As[ar][ac + 1] = a4.y;
        As[ar][ac + 2] = a4.z; As[ar][ac + 3] = a4.w;
        float4 b4 = *(const float4*)(B + (size_t)(kt + br) * N + col0 + bc);
        *(float4*)&Bs[br][bc] = b4;
        __syncthreads();

        #pragma unroll
        for (int kk = 0; kk < 16; kk++) {
            float a0 = As[ty * 4 + 0][kk];
            float a1 = As[ty * 4 + 1][kk];
            float a2 = As[ty * 4 + 2][kk];
            float a3 = As[ty * 4 + 3][kk];
            float4 bv = *(float4*)&Bs[kk][tx * 4];
            acc[0][0] += a0 * bv.x; acc[0][1] += a0 * bv.y; acc[0][2] += a0 * bv.z; acc[0][3] += a0 * bv.w;
            acc[1][0] += a1 * bv.x; acc[1][1] += a1 * bv.y; acc[1][2] += a1 * bv.z; acc[1][3] += a1 * bv.w;
            acc[2][0] += a2 * bv.x; acc[2][1] += a2 * bv.y; acc[2][2] += a2 * bv.z; acc[2][3] += a2 * bv.w;
            acc[3][0] += a3 * bv.x; acc[3][1] += a3 * bv.y; acc[3][2] += a3 * bv.z; acc[3][3] += a3 * bv.w;
        }
        __syncthreads();
    }

    #pragma unroll
    for (int i = 0; i < 4; i++) {
        int r = row0 + ty * 4 + i;
        #pragma unroll
        for (int j = 0; j < 4; j++) {
            int c = col0 + tx * 4 + j;
            float v = (acc[i][j] + bias[c]) * alpha;
            if (RESID) v += R[(size_t)r * N + c];
            if (GELU)  v = 0.5f * v * (1.0f + erff(v * 0.70710678118654752f));
            C[(size_t)r * N + c] = v;
        }
    }
}

// ---------------------------------------------------------------------------
// Attention: one CTA per (b, h). K/V staged in padded SMEM (stride 65).
// One warp per query row: scores, softmax (warp shuffles), probs @ V.
// Writes attn_weights [B,H,N,N] and pre_proj [B,N,H*hd] (== d_out regions).
// ---------------------------------------------------------------------------
#define ATTN_SMEM_FLOATS (Ns*65*2 + 8*64 + 8*Ns)
#define ATTN_SMEM_BYTES  (ATTN_SMEM_FLOATS * 4)

__global__ void attn_kernel(const float* __restrict__ q,
                            const float* __restrict__ k,
                            const float* __restrict__ v,
                            float* __restrict__ attn_w,
                            float* __restrict__ pre_proj) {
    extern __shared__ float sm[];
    float* Ks = sm;                 // [197][65]
    float* Vs = Ks + Ns * 65;       // [197][65]
    float* Qr = Vs + Ns * 65;       // [8][64]
    float* Sc = Qr + 8 * 64;        // [8][197]

    int bh = blockIdx.x;
    int b = bh / Hh, h = bh % Hh;
    int tid = threadIdx.x, lane = tid & 31, warp = tid >> 5;

    size_t base = (size_t)b * Ns * Dm + (size_t)h * HDh;

    for (int idx = tid; idx < Ns * HDh; idx += 256) {
        int r = idx >> 6, c = idx & 63;
        Ks[r * 65 + c] = k[base + (size_t)r * Dm + c];
        Vs[r * 65 + c] = v[base + (size_t)r * Dm + c];
    }
    __syncthreads();

    size_t awbase = (size_t)bh * Ns * Ns;

    for (int qi = warp; qi < Ns; qi += 8) {
        Qr[warp * 64 + lane]      = q[base + (size_t)qi * Dm + lane];
        Qr[warp * 64 + lane + 32] = q[base + (size_t)qi * Dm + lane + 32];
        __syncwarp();

        float mx = -1e30f;
        for (int kk = lane; kk < Ns; kk += 32) {
            float dot = 0.f;
            #pragma unroll
            for (int d = 0; d < 64; d++)
                dot += Qr[warp * 64 + d] * Ks[kk * 65 + d];
            Sc[warp * Ns + kk] = dot;
            mx = fmaxf(mx, dot);
        }
        #pragma unroll
        for (int o = 16; o > 0; o >>= 1)
            mx = fmaxf(mx, __shfl_xor_sync(0xffffffffu, mx, o));

        float sum = 0.f;
        for (int kk = lane; kk < Ns; kk += 32) {
            float e = __expf(Sc[warp * Ns + kk] - mx);
            Sc[warp * Ns + kk] = e;
            sum += e;
        }
        #pragma unroll
        for (int o = 16; o > 0; o >>= 1)
            sum += __shfl_xor_sync(0xffffffffu, sum, o);
        float inv = 1.0f / sum;

        for (int kk = lane; kk < Ns; kk += 32) {
            float p = Sc[warp * Ns + kk] * inv;
            Sc[warp * Ns + kk] = p;
            attn_w[awbase + (size_t)qi * Ns + kk] = p;
        }
        __syncwarp();

        for (int d = lane; d < HDh; d += 32) {
            float acc = 0.f;
            for (int kk = 0; kk < Ns; kk++)
                acc += Sc[warp * Ns + kk] * Vs[kk * 65 + d];
            pre_proj[base + (size_t)qi * Dm + d] = acc;
        }
        __syncwarp();
    }
}

// ---------------------------------------------------------------------------
// Launch
// ---------------------------------------------------------------------------
extern "C" void kernel_launch(void* const* d_in, const int* in_sizes, int n_in,
                              void* d_out, int out_size) {
    const float* x     = (const float*)d_in[0];
    const float* ln1_g = (const float*)d_in[1];
    const float* ln1_b = (const float*)d_in[2];
    const float* wq    = (const float*)d_in[3];
    const float* bq    = (const float*)d_in[4];
    const float* wk    = (const float*)d_in[5];
    const float* bk    = (const float*)d_in[6];
    const float* wv    = (const float*)d_in[7];
    const float* bv    = (const float*)d_in[8];
    const float* wo    = (const float*)d_in[9];
    const float* bo    = (const float*)d_in[10];
    const float* ln2_g = (const float*)d_in[11];
    const float* ln2_b = (const float*)d_in[12];
    const float* w1    = (const float*)d_in[13];
    const float* b1    = (const float*)d_in[14];
    const float* w2    = (const float*)d_in[15];
    const float* b2    = (const float*)d_in[16];

    float* out = (float*)d_out;
    const size_t S = (size_t)Mrows * Dm;    // 9,682,944
    float* pre_proj = out;                  // [B,N,D]
    float* hidden   = out + S;              // [B,N,D]
    float* attn_w   = out + 2 * S;          // [B,H,N,N]

    float *h, *qq, *kk, *vv, *hs, *ffn;
    cudaGetSymbolAddress((void**)&h,   g_h);
    cudaGetSymbolAddress((void**)&qq,  g_q);
    cudaGetSymbolAddress((void**)&kk,  g_k);
    cudaGetSymbolAddress((void**)&vv,  g_v);
    cudaGetSymbolAddress((void**)&hs,  g_hs);
    cudaGetSymbolAddress((void**)&ffn, g_ffn);

    cudaFuncSetAttribute(attn_kernel,
                         cudaFuncAttributeMaxDynamicSharedMemorySize,
                         ATTN_SMEM_BYTES);

    const float scale = 0.125f;  // 64^-0.5

    // 1) h = LN1(x)
    ln_kernel<<<Mrows, 256>>>(x, ln1_g, ln1_b, h);

    // 2) q,k,v projections
    dim3 gD(Dm / 64, Mrows / 64);
    sgemm_kernel<false, false><<<gD, 256>>>(h, wq, bq, nullptr, qq, Mrows, Dm, Dm, scale);
    sgemm_kernel<false, false><<<gD, 256>>>(h, wk, bk, nullptr, kk, Mrows, Dm, Dm, 1.0f);
    sgemm_kernel<false, false><<<gD, 256>>>(h, wv, bv, nullptr, vv, Mrows, Dm, Dm, 1.0f);

    // 3) attention: writes attn_w and pre_proj
    attn_kernel<<<Bsz * Hh, 256, ATTN_SMEM_BYTES>>>(qq, kk, vv, attn_w, pre_proj);

    // 4) hs = x + pre_proj @ wo + bo
    sgemm_kernel<true, false><<<gD, 256>>>(pre_proj, wo, bo, x, hs, Mrows, Dm, Dm, 1.0f);

    // 5) h = LN2(hs)
    ln_kernel<<<Mrows, 256>>>(hs, ln2_g, ln2_b, h);

    // 6) ffn = gelu(h @ w1 + b1)
    dim3 gF(DFFc / 64, Mrows / 64);
    sgemm_kernel<false, true><<<gF, 256>>>(h, w1, b1, nullptr, ffn, Mrows, DFFc, Dm, 1.0f);

    // 7) hidden = hs + ffn @ w2 + b2
    sgemm_kernel<true, false><<<gD, 256>>>(ffn, w2, b2, hs, hidden, Mrows, Dm, DFFc, 1.0f);
}

// round 5
// speedup vs baseline: 2.4466x; 2.4466x over previous
#include <cuda_runtime.h>
#include <math.h>
#include <stddef.h>
#include <stdint.h>

// Problem constants
#define Bsz 64
#define Ns  197
#define Dm  768
#define Hh  12
#define HDh 64
#define DFFc 3072
#define Mrows (Bsz*Ns)          // 12608

// ---------------------------------------------------------------------------
// Scratch (device globals: no allocations allowed)
// ---------------------------------------------------------------------------
__device__ float g_h  [Mrows*Dm];
__device__ float g_q  [Mrows*Dm];
__device__ float g_k  [Mrows*Dm];
__device__ float g_v  [Mrows*Dm];
__device__ float g_hs [Mrows*Dm];
__device__ float g_ffn[(size_t)Mrows*DFFc];
// transposed weights [N,K]
__device__ float g_wqT[Dm*Dm];
__device__ float g_wkT[Dm*Dm];
__device__ float g_wvT[Dm*Dm];
__device__ float g_woT[Dm*Dm];
__device__ float g_w1T[Dm*DFFc];
__device__ float g_w2T[Dm*DFFc];

// ---------------------------------------------------------------------------
// tf32 helpers
// ---------------------------------------------------------------------------
__device__ __forceinline__ uint32_t f2tf32(float x) {
    uint32_t u;
    asm("cvt.rna.tf32.f32 %0, %1;" : "=r"(u) : "f"(x));
    return u;
}

__device__ __forceinline__ void mma_tf32(float* d, const uint32_t* a,
                                         uint32_t b0, uint32_t b1) {
    asm volatile(
        "mma.sync.aligned.m16n8k8.row.col.f32.tf32.tf32.f32 "
        "{%0,%1,%2,%3}, {%4,%5,%6,%7}, {%8,%9}, {%0,%1,%2,%3};"
        : "+f"(d[0]), "+f"(d[1]), "+f"(d[2]), "+f"(d[3])
        : "r"(a[0]), "r"(a[1]), "r"(a[2]), "r"(a[3]), "r"(b0), "r"(b1));
}

// ---------------------------------------------------------------------------
// GEMM: C = act((A @ Bt^T + bias) * alpha + resid)
// A: [M,K] row-major. Bt: [N,K] row-major. Tile 128x128x16.
// 8 warps as 4(m) x 2(n); warp tile 32x64 -> 2x8 m16n8k8 mmas.
// SMEM pitch 20 floats: fragment loads conflict-free.
// ---------------------------------------------------------------------------
template<bool RESID, bool GELU>
__global__ __launch_bounds__(256)
void mma_gemm(const float* __restrict__ A, const float* __restrict__ Bt,
              const float* __restrict__ bias, const float* __restrict__ R,
              float* __restrict__ C, int M, int N, int K, float alpha)
{
    __shared__ uint32_t As[2][128][20];
    __shared__ uint32_t Bs[2][128][20];

    const int tid = threadIdx.x;
    const int w = tid >> 5, lane = tid & 31;
    const int g = lane >> 2, tq = lane & 3;
    const int wm = w & 3, wn = w >> 2;
    const int row0 = blockIdx.y * 128, col0 = blockIdx.x * 128;

    // staging coords: thread covers rows (tid>>2) and (tid>>2)+64, cols (tid&3)*4..+3
    const int srow = tid >> 2;
    const int scol = (tid & 3) * 4;
    int ga0 = row0 + srow;      if (ga0 >= M) ga0 = M - 1;
    int ga1 = row0 + srow + 64; if (ga1 >= M) ga1 = M - 1;
    const float* pA0 = A + (size_t)ga0 * K + scol;
    const float* pA1 = A + (size_t)ga1 * K + scol;
    const float* pB0 = Bt + (size_t)(col0 + srow) * K + scol;
    const float* pB1 = Bt + (size_t)(col0 + srow + 64) * K + scol;

    float acc[2][8][4];
    #pragma unroll
    for (int mt = 0; mt < 2; mt++)
        #pragma unroll
        for (int nt = 0; nt < 8; nt++)
            #pragma unroll
            for (int i = 0; i < 4; i++) acc[mt][nt][i] = 0.f;

    const int KC = K >> 4;
    float4 ra0, ra1, rb0, rb1;

    // prefetch chunk 0
    ra0 = *(const float4*)pA0; ra1 = *(const float4*)pA1;
    rb0 = *(const float4*)pB0; rb1 = *(const float4*)pB1;

    #define STS_CHUNK(buf) do { \
        As[buf][srow     ][scol+0] = f2tf32(ra0.x); As[buf][srow     ][scol+1] = f2tf32(ra0.y); \
        As[buf][srow     ][scol+2] = f2tf32(ra0.z); As[buf][srow     ][scol+3] = f2tf32(ra0.w); \
        As[buf][srow + 64][scol+0] = f2tf32(ra1.x); As[buf][srow + 64][scol+1] = f2tf32(ra1.y); \
        As[buf][srow + 64][scol+2] = f2tf32(ra1.z); As[buf][srow + 64][scol+3] = f2tf32(ra1.w); \
        Bs[buf][srow     ][scol+0] = f2tf32(rb0.x); Bs[buf][srow     ][scol+1] = f2tf32(rb0.y); \
        Bs[buf][srow     ][scol+2] = f2tf32(rb0.z); Bs[buf][srow     ][scol+3] = f2tf32(rb0.w); \
        Bs[buf][srow + 64][scol+0] = f2tf32(rb1.x); Bs[buf][srow + 64][scol+1] = f2tf32(rb1.y); \
        Bs[buf][srow + 64][scol+2] = f2tf32(rb1.z); Bs[buf][srow + 64][scol+3] = f2tf32(rb1.w); \
    } while (0)

    STS_CHUNK(0);
    __syncthreads();

    for (int ck = 0; ck < KC; ck++) {
        const int cbuf = ck & 1;
        // prefetch next chunk from global
        if (ck + 1 < KC) {
            const int off = (ck + 1) * 16;
            ra0 = *(const float4*)(pA0 + off); ra1 = *(const float4*)(pA1 + off);
            rb0 = *(const float4*)(pB0 + off); rb1 = *(const float4*)(pB1 + off);
        }
        // compute on current buffer: 2 k-steps of 8
        #pragma unroll
        for (int ks = 0; ks < 2; ks++) {
            const int k0 = ks * 8;
            uint32_t afr[2][4];
            #pragma unroll
            for (int mt = 0; mt < 2; mt++) {
                const int rm = wm * 32 + mt * 16;
                afr[mt][0] = As[cbuf][rm + g    ][k0 + tq];
                afr[mt][1] = As[cbuf][rm + 8 + g][k0 + tq];
                afr[mt][2] = As[cbuf][rm + g    ][k0 + 4 + tq];
                afr[mt][3] = As[cbuf][rm + 8 + g][k0 + 4 + tq];
            }
            #pragma unroll
            for (int nt = 0; nt < 8; nt++) {
                const int rn = wn * 64 + nt * 8 + g;
                uint32_t b0 = Bs[cbuf][rn][k0 + tq];
                uint32_t b1 = Bs[cbuf][rn][k0 + 4 + tq];
                mma_tf32(acc[0][nt], afr[0], b0, b1);
                mma_tf32(acc[1][nt], afr[1], b0, b1);
            }
        }
        if (ck + 1 < KC) {
            STS_CHUNK((ck + 1) & 1);
            __syncthreads();
        }
    }
    #undef STS_CHUNK

    // Epilogue: each thread owns (row g / g+8, cols 2*tq, 2*tq+1) per mma tile
    #pragma unroll
    for (int mt = 0; mt < 2; mt++) {
        #pragma unroll
        for (int nt = 0; nt < 8; nt++) {
            const int cc = col0 + wn * 64 + nt * 8 + 2 * tq;
            const float b0 = bias[cc], b1 = bias[cc + 1];
            #pragma unroll
            for (int half = 0; half < 2; half++) {
                const int r_ = row0 + wm * 32 + mt * 16 + g + half * 8;
                if (r_ < M) {
                    float v0 = (acc[mt][nt][half * 2 + 0] + b0) * alpha;
                    float v1 = (acc[mt][nt][half * 2 + 1] + b1) * alpha;
                    if (RESID) {
                        const float* rp = R + (size_t)r_ * N + cc;
                        v0 += rp[0]; v1 += rp[1];
                    }
                    if (GELU) {
                        v0 = 0.5f * v0 * (1.0f + erff(v0 * 0.70710678118654752f));
                        v1 = 0.5f * v1 * (1.0f + erff(v1 * 0.70710678118654752f));
                    }
                    *(float2*)(C + (size_t)r_ * N + cc) = make_float2(v0, v1);
                }
            }
        }
    }
}

// ---------------------------------------------------------------------------
// Weight transpose: out[c][r] = in[r][c]
// ---------------------------------------------------------------------------
__global__ void transpose_kernel(const float* __restrict__ in, float* __restrict__ out,
                                 int rows, int cols) {
    __shared__ float t[32][33];
    int bx = blockIdx.x * 32, by = blockIdx.y * 32;
    int x = bx + threadIdx.x, y = by + threadIdx.y;
    #pragma unroll
    for (int i = 0; i < 32; i += 8)
        t[threadIdx.y + i][threadIdx.x] = in[(size_t)(y + i) * cols + x];
    __syncthreads();
    x = by + threadIdx.x; y = bx + threadIdx.y;
    #pragma unroll
    for (int i = 0; i < 32; i += 8)
        out[(size_t)(y + i) * rows + x] = t[threadIdx.x][threadIdx.y + i];
}

// ---------------------------------------------------------------------------
// LayerNorm: one CTA (256 threads) per row of 768
// ---------------------------------------------------------------------------
__global__ void ln_kernel(const float* __restrict__ x,
                          const float* __restrict__ g,
                          const float* __restrict__ b,
                          float* __restrict__ out) {
    int row = blockIdx.x;
    const float* xr = x + (size_t)row * Dm;
    float s = 0.f, s2 = 0.f;
    for (int i = threadIdx.x; i < Dm; i += 256) {
        float v = xr[i];
        s += v; s2 += v * v;
    }
    __shared__ float r1[256], r2[256];
    r1[threadIdx.x] = s; r2[threadIdx.x] = s2;
    __syncthreads();
    #pragma unroll
    for (int o = 128; o > 0; o >>= 1) {
        if (threadIdx.x < o) {
            r1[threadIdx.x] += r1[threadIdx.x + o];
            r2[threadIdx.x] += r2[threadIdx.x + o];
        }
        __syncthreads();
    }
    float mu  = r1[0] * (1.0f / Dm);
    float var = r2[0] * (1.0f / Dm) - mu * mu;
    float inv = rsqrtf(var + 1e-5f);
    float* orow = out + (size_t)row * Dm;
    for (int i = threadIdx.x; i < Dm; i += 256)
        orow[i] = (xr[i] - mu) * inv * g[i] + b[i];
}

// ---------------------------------------------------------------------------
// Attention: one CTA per (b, h). K/V in SMEM pitch 68 (16B aligned rows).
// One warp per query row; float4 dots, float2 P@V.
// ---------------------------------------------------------------------------
#define KV_PITCH 68
#define SC_PITCH 200
#define ATTN_SMEM_FLOATS (Ns*KV_PITCH*2 + 8*64 + 8*SC_PITCH)
#define ATTN_SMEM_BYTES  (ATTN_SMEM_FLOATS * 4)

__global__ void attn_kernel(const float* __restrict__ q,
                            const float* __restrict__ k,
                            const float* __restrict__ v,
                            float* __restrict__ attn_w,
                            float* __restrict__ pre_proj) {
    extern __shared__ float sm[];
    float* Ks = sm;                        // [197][68]
    float* Vs = Ks + Ns * KV_PITCH;        // [197][68]
    float* Qr = Vs + Ns * KV_PITCH;        // [8][64]
    float* Sc = Qr + 8 * 64;               // [8][200]

    int bh = blockIdx.x;
    int b = bh / Hh, h = bh % Hh;
    int tid = threadIdx.x, lane = tid & 31, warp = tid >> 5;

    size_t base = (size_t)b * Ns * Dm + (size_t)h * HDh;

    for (int idx = tid; idx < Ns * 16; idx += 256) {
        int r = idx >> 4, f = idx & 15;
        *(float4*)(Ks + r * KV_PITCH + f * 4) = *(const float4*)(k + base + (size_t)r * Dm + f * 4);
        *(float4*)(Vs + r * KV_PITCH + f * 4) = *(const float4*)(v + base + (size_t)r * Dm + f * 4);
    }
    __syncthreads();

    size_t awbase = (size_t)bh * Ns * Ns;

    for (int qi = warp; qi < Ns; qi += 8) {
        Qr[warp * 64 + lane]      = q[base + (size_t)qi * Dm + lane];
        Qr[warp * 64 + lane + 32] = q[base + (size_t)qi * Dm + lane + 32];
        __syncwarp();

        const float4* Q4 = (const float4*)(Qr + warp * 64);
        float mx = -1e30f;
        for (int kk = lane; kk < Ns; kk += 32) {
            const float4* K4 = (const float4*)(Ks + kk * KV_PITCH);
            float dot = 0.f;
            #pragma unroll
            for (int d4 = 0; d4 < 16; d4++) {
                float4 qv = Q4[d4], kv = K4[d4];
                dot += qv.x * kv.x + qv.y * kv.y + qv.z * kv.z + qv.w * kv.w;
            }
            Sc[warp * SC_PITCH + kk] = dot;
            mx = fmaxf(mx, dot);
        }
        #pragma unroll
        for (int o = 16; o > 0; o >>= 1)
            mx = fmaxf(mx, __shfl_xor_sync(0xffffffffu, mx, o));

        float sum = 0.f;
        for (int kk = lane; kk < Ns; kk += 32) {
            float e = __expf(Sc[warp * SC_PITCH + kk] - mx);
            Sc[warp * SC_PITCH + kk] = e;
            sum += e;
        }
        #pragma unroll
        for (int o = 16; o > 0; o >>= 1)
            sum += __shfl_xor_sync(0xffffffffu, sum, o);
        float inv = 1.0f / sum;

        for (int kk = lane; kk < Ns; kk += 32) {
            float p = Sc[warp * SC_PITCH + kk] * inv;
            Sc[warp * SC_PITCH + kk] = p;
            attn_w[awbase + (size_t)qi * Ns + kk] = p;
        }
        __syncwarp();

        float2 acc = make_float2(0.f, 0.f);
        const float* ScW = Sc + warp * SC_PITCH;
        const float* Vp = Vs + lane * 2;
        for (int kk = 0; kk < Ns; kk++) {
            float p = ScW[kk];
            float2 vv = *(const float2*)(Vp + kk * KV_PITCH);
            acc.x += p * vv.x;
            acc.y += p * vv.y;
        }
        *(float2*)(pre_proj + base + (size_t)qi * Dm + lane * 2) = acc;
        __syncwarp();
    }
}

// ---------------------------------------------------------------------------
// Launch
// ---------------------------------------------------------------------------
extern "C" void kernel_launch(void* const* d_in, const int* in_sizes, int n_in,
                              void* d_out, int out_size) {
    const float* x     = (const float*)d_in[0];
    const float* ln1_g = (const float*)d_in[1];
    const float* ln1_b = (const float*)d_in[2];
    const float* wq    = (const float*)d_in[3];
    const float* bq    = (const float*)d_in[4];
    const float* wk    = (const float*)d_in[5];
    const float* bk    = (const float*)d_in[6];
    const float* wv    = (const float*)d_in[7];
    const float* bv    = (const float*)d_in[8];
    const float* wo    = (const float*)d_in[9];
    const float* bo    = (const float*)d_in[10];
    const float* ln2_g = (const float*)d_in[11];
    const float* ln2_b = (const float*)d_in[12];
    const float* w1    = (const float*)d_in[13];
    const float* b1    = (const float*)d_in[14];
    const float* w2    = (const float*)d_in[15];
    const float* b2    = (const float*)d_in[16];

    float* out = (float*)d_out;
    const size_t S = (size_t)Mrows * Dm;
    float* pre_proj = out;
    float* hidden   = out + S;
    float* attn_w   = out + 2 * S;

    float *h, *qq, *kk, *vv, *hs, *ffn;
    float *wqT, *wkT, *wvT, *woT, *w1T, *w2T;
    cudaGetSymbolAddress((void**)&h,   g_h);
    cudaGetSymbolAddress((void**)&qq,  g_q);
    cudaGetSymbolAddress((void**)&kk,  g_k);
    cudaGetSymbolAddress((void**)&vv,  g_v);
    cudaGetSymbolAddress((void**)&hs,  g_hs);
    cudaGetSymbolAddress((void**)&ffn, g_ffn);
    cudaGetSymbolAddress((void**)&wqT, g_wqT);
    cudaGetSymbolAddress((void**)&wkT, g_wkT);
    cudaGetSymbolAddress((void**)&wvT, g_wvT);
    cudaGetSymbolAddress((void**)&woT, g_woT);
    cudaGetSymbolAddress((void**)&w1T, g_w1T);
    cudaGetSymbolAddress((void**)&w2T, g_w2T);

    cudaFuncSetAttribute(attn_kernel, cudaFuncAttributeMaxDynamicSharedMemorySize, ATTN_SMEM_BYTES);

    const float scale = 0.125f;

    // 0) transpose weights to [N,K]
    dim3 tb(32, 8);
    transpose_kernel<<<dim3(Dm / 32, Dm / 32), tb>>>(wq, wqT, Dm, Dm);
    transpose_kernel<<<dim3(Dm / 32, Dm / 32), tb>>>(wk, wkT, Dm, Dm);
    transpose_kernel<<<dim3(Dm / 32, Dm / 32), tb>>>(wv, wvT, Dm, Dm);
    transpose_kernel<<<dim3(Dm / 32, Dm / 32), tb>>>(wo, woT, Dm, Dm);
    transpose_kernel<<<dim3(DFFc / 32, Dm / 32), tb>>>(w1, w1T, Dm, DFFc);   // -> [3072,768]
    transpose_kernel<<<dim3(Dm / 32, DFFc / 32), tb>>>(w2, w2T, DFFc, Dm);   // -> [768,3072]

    // 1) h = LN1(x)
    ln_kernel<<<Mrows, 256>>>(x, ln1_g, ln1_b, h);

    const int MT = (Mrows + 127) / 128;  // 99

    // 2) q,k,v projections
    dim3 gD(Dm / 128, MT);
    mma_gemm<false, false><<<gD, 256>>>(h, wqT, bq, nullptr, qq, Mrows, Dm, Dm, scale);
    mma_gemm<false, false><<<gD, 256>>>(h, wkT, bk, nullptr, kk, Mrows, Dm, Dm, 1.0f);
    mma_gemm<false, false><<<gD, 256>>>(h, wvT, bv, nullptr, vv, Mrows, Dm, Dm, 1.0f);

    // 3) attention
    attn_kernel<<<Bsz * Hh, 256, ATTN_SMEM_BYTES>>>(qq, kk, vv, attn_w, pre_proj);

    // 4) hs = x + pre_proj @ wo + bo
    mma_gemm<true, false><<<gD, 256>>>(pre_proj, woT, bo, x, hs, Mrows, Dm, Dm, 1.0f);

    // 5) h = LN2(hs)
    ln_kernel<<<Mrows, 256>>>(hs, ln2_g, ln2_b, h);

    // 6) ffn = gelu(h @ w1 + b1)
    dim3 gF(DFFc / 128, MT);
    mma_gemm<false, true><<<gF, 256>>>(h, w1T, b1, nullptr, ffn, Mrows, DFFc, Dm, 1.0f);

    // 7) hidden = hs + ffn @ w2 + b2
    mma_gemm<true, false><<<gD, 256>>>(ffn, w2T, b2, hs, hidden, Mrows, Dm, DFFc, 1.0f);
}

// round 6
// speedup vs baseline: 3.2183x; 1.3154x over previous
#include <cuda_runtime.h>
#include <cuda_fp16.h>
#include <math.h>
#include <stddef.h>
#include <stdint.h>

// Problem constants
#define Bsz 64
#define Ns  197
#define Dm  768
#define Hh  12
#define HDh 64
#define DFFc 3072
#define Mrows (Bsz*Ns)          // 12608
#define QKVS 2304               // fused qkv row stride

// ---------------------------------------------------------------------------
// Scratch (device globals: no allocations allowed)
// ---------------------------------------------------------------------------
__device__ __half g_h_h  [Mrows*Dm];            // LN output (half), reused LN1/LN2
__device__ float  g_qkv  [(size_t)Mrows*QKVS];  // fused q|k|v fp32
__device__ __half g_pp_h [Mrows*Dm];            // half copy of pre_proj
__device__ float  g_hs   [Mrows*Dm];            // residual after attention
__device__ __half g_ffn_h[(size_t)Mrows*DFFc];  // gelu(h2@w1+b1) half
// transposed half weights [N,K]
__device__ __half g_wqkvT[QKVS*Dm];             // rows: wq*0.125 | wk | wv
__device__ __half g_woT  [Dm*Dm];
__device__ __half g_w1T  [DFFc*Dm];
__device__ __half g_w2T  [Dm*DFFc];
__device__ float  g_bqkv [QKVS];

// ---------------------------------------------------------------------------
// fp16 mma m16n8k16
// ---------------------------------------------------------------------------
__device__ __forceinline__ void mma_f16(float* d, const uint32_t* a,
                                        uint32_t b0, uint32_t b1) {
    asm volatile(
        "mma.sync.aligned.m16n8k16.row.col.f32.f16.f16.f32 "
        "{%0,%1,%2,%3}, {%4,%5,%6,%7}, {%8,%9}, {%0,%1,%2,%3};"
        : "+f"(d[0]), "+f"(d[1]), "+f"(d[2]), "+f"(d[3])
        : "r"(a[0]), "r"(a[1]), "r"(a[2]), "r"(a[3]), "r"(b0), "r"(b1));
}

// ---------------------------------------------------------------------------
// HGEMM: C = act(A @ Bt^T + bias [+ R])
// A: [M,K] half row-major. Bt: [N,K] half row-major. Tile 128x128x16.
// 8 warps 4(m) x 2(n); warp tile 32x64 -> 2x8 m16n8k16 mmas per chunk.
// SMEM pitch 20 half2: fragment loads provably conflict-free.
// OUTH: write __half, else float.
// ---------------------------------------------------------------------------
template<bool RESID, bool GELU, bool OUTH>
__global__ __launch_bounds__(256)
void hgemm(const __half* __restrict__ A, const __half* __restrict__ Bt,
           const float* __restrict__ bias, const float* __restrict__ R,
           void* __restrict__ Cout, int M, int N, int K)
{
    __shared__ uint32_t As[2][128][20];
    __shared__ uint32_t Bs[2][128][20];

    const int tid = threadIdx.x;
    const int w = tid >> 5, lane = tid & 31;
    const int g = lane >> 2, tq = lane & 3;
    const int wm = w & 3, wn = w >> 2;
    const int row0 = blockIdx.y * 128, col0 = blockIdx.x * 128;

    // staging: thread covers (row tid>>1, halves (tid&1)*8 .. +7) per chunk
    const int srow = tid >> 1, sseg = tid & 1;
    int ga = row0 + srow; if (ga >= M) ga = M - 1;
    const __half* pA = A + (size_t)ga * K + sseg * 8;
    const __half* pB = Bt + (size_t)(col0 + srow) * K + sseg * 8;

    float acc[2][8][4];
    #pragma unroll
    for (int mt = 0; mt < 2; mt++)
        #pragma unroll
        for (int nt = 0; nt < 8; nt++)
            #pragma unroll
            for (int i = 0; i < 4; i++) acc[mt][nt][i] = 0.f;

    const int KC = K >> 4;
    uint4 ra, rb;
    ra = *(const uint4*)pA;
    rb = *(const uint4*)pB;
    *(uint4*)&As[0][srow][sseg * 4] = ra;
    *(uint4*)&Bs[0][srow][sseg * 4] = rb;
    __syncthreads();

    for (int ck = 0; ck < KC; ck++) {
        const int cb = ck & 1;
        if (ck + 1 < KC) {
            const int off = (ck + 1) * 16;
            ra = *(const uint4*)(pA + off);
            rb = *(const uint4*)(pB + off);
        }
        uint32_t afr[2][4];
        #pragma unroll
        for (int mt = 0; mt < 2; mt++) {
            const int rm = wm * 32 + mt * 16;
            afr[mt][0] = As[cb][rm + g    ][tq];
            afr[mt][1] = As[cb][rm + 8 + g][tq];
            afr[mt][2] = As[cb][rm + g    ][tq + 4];
            afr[mt][3] = As[cb][rm + 8 + g][tq + 4];
        }
        #pragma unroll
        for (int nt = 0; nt < 8; nt++) {
            const int rn = wn * 64 + nt * 8 + g;
            uint32_t b0 = Bs[cb][rn][tq];
            uint32_t b1 = Bs[cb][rn][tq + 4];
            mma_f16(acc[0][nt], afr[0], b0, b1);
            mma_f16(acc[1][nt], afr[1], b0, b1);
        }
        if (ck + 1 < KC) {
            *(uint4*)&As[(ck + 1) & 1][srow][sseg * 4] = ra;
            *(uint4*)&Bs[(ck + 1) & 1][srow][sseg * 4] = rb;
            __syncthreads();
        }
    }

    // Epilogue: thread owns rows g/g+8, cols 2tq..2tq+1 per mma tile
    #pragma unroll
    for (int mt = 0; mt < 2; mt++) {
        #pragma unroll
        for (int nt = 0; nt < 8; nt++) {
            const int cc = col0 + wn * 64 + nt * 8 + 2 * tq;
            const float b0 = bias[cc], b1 = bias[cc + 1];
            #pragma unroll
            for (int half_ = 0; half_ < 2; half_++) {
                const int r_ = row0 + wm * 32 + mt * 16 + g + half_ * 8;
                if (r_ < M) {
                    float v0 = acc[mt][nt][half_ * 2 + 0] + b0;
                    float v1 = acc[mt][nt][half_ * 2 + 1] + b1;
                    if (RESID) {
                        const float* rp = R + (size_t)r_ * N + cc;
                        v0 += rp[0]; v1 += rp[1];
                    }
                    if (GELU) {
                        v0 = 0.5f * v0 * (1.0f + erff(v0 * 0.70710678118654752f));
                        v1 = 0.5f * v1 * (1.0f + erff(v1 * 0.70710678118654752f));
                    }
                    if (OUTH) {
                        *(__half2*)((__half*)Cout + (size_t)r_ * N + cc) =
                            __floats2half2_rn(v0, v1);
                    } else {
                        *(float2*)((float*)Cout + (size_t)r_ * N + cc) =
                            make_float2(v0, v1);
                    }
                }
            }
        }
    }
}

// ---------------------------------------------------------------------------
// Transpose + convert to half (+scale): out[c][r] = half(in[r][c] * scale)
// ---------------------------------------------------------------------------
__global__ void transpose_half_kernel(const float* __restrict__ in,
                                      __half* __restrict__ out,
                                      int rows, int cols, float scale) {
    __shared__ float t[32][33];
    int bx = blockIdx.x * 32, by = blockIdx.y * 32;
    int x = bx + threadIdx.x, y = by + threadIdx.y;
    #pragma unroll
    for (int i = 0; i < 32; i += 8)
        t[threadIdx.y + i][threadIdx.x] = in[(size_t)(y + i) * cols + x];
    __syncthreads();
    x = by + threadIdx.x; y = bx + threadIdx.y;
    #pragma unroll
    for (int i = 0; i < 32; i += 8)
        out[(size_t)(y + i) * rows + x] = __float2half(t[threadIdx.x][threadIdx.y + i] * scale);
}

// build fused qkv bias (q scaled)
__global__ void bias_qkv_kernel(const float* __restrict__ bq,
                                const float* __restrict__ bk,
                                const float* __restrict__ bv,
                                float* __restrict__ out) {
    int i = blockIdx.x * 256 + threadIdx.x;
    if (i < Dm)            out[i] = bq[i] * 0.125f;
    else if (i < 2 * Dm)   out[i] = bk[i - Dm];
    else if (i < 3 * Dm)   out[i] = bv[i - 2 * Dm];
}

// ---------------------------------------------------------------------------
// LayerNorm -> half output
// ---------------------------------------------------------------------------
__global__ void ln_kernel(const float* __restrict__ x,
                          const float* __restrict__ g,
                          const float* __restrict__ b,
                          __half* __restrict__ out) {
    int row = blockIdx.x;
    const float* xr = x + (size_t)row * Dm;
    float s = 0.f, s2 = 0.f;
    for (int i = threadIdx.x; i < Dm; i += 256) {
        float v = xr[i];
        s += v; s2 += v * v;
    }
    __shared__ float r1[256], r2[256];
    r1[threadIdx.x] = s; r2[threadIdx.x] = s2;
    __syncthreads();
    #pragma unroll
    for (int o = 128; o > 0; o >>= 1) {
        if (threadIdx.x < o) {
            r1[threadIdx.x] += r1[threadIdx.x + o];
            r2[threadIdx.x] += r2[threadIdx.x + o];
        }
        __syncthreads();
    }
    float mu  = r1[0] * (1.0f / Dm);
    float var = r2[0] * (1.0f / Dm) - mu * mu;
    float inv = rsqrtf(var + 1e-5f);
    __half* orow = out + (size_t)row * Dm;
    for (int i = threadIdx.x; i < Dm; i += 256)
        orow[i] = __float2half((xr[i] - mu) * inv * g[i] + b[i]);
}

// ---------------------------------------------------------------------------
// Attention: one CTA per (b, h). q/k/v from fused buffer (stride QKVS).
// Writes attn_weights + pre_proj (fp32, d_out) + half copy of pre_proj.
// ---------------------------------------------------------------------------
#define KV_PITCH 68
#define SC_PITCH 200
#define ATTN_SMEM_FLOATS (Ns*KV_PITCH*2 + 8*64 + 8*SC_PITCH)
#define ATTN_SMEM_BYTES  (ATTN_SMEM_FLOATS * 4)

__global__ void attn_kernel(const float* __restrict__ qkv,
                            float* __restrict__ attn_w,
                            float* __restrict__ pre_proj,
                            __half* __restrict__ pp_h) {
    extern __shared__ float sm[];
    float* Ks = sm;
    float* Vs = Ks + Ns * KV_PITCH;
    float* Qr = Vs + Ns * KV_PITCH;
    float* Sc = Qr + 8 * 64;

    int bh = blockIdx.x;
    int b = bh / Hh, h = bh % Hh;
    int tid = threadIdx.x, lane = tid & 31, warp = tid >> 5;

    size_t baseq = (size_t)b * Ns * QKVS + (size_t)h * HDh;
    const float* qp = qkv + baseq;
    const float* kp = qkv + baseq + Dm;
    const float* vp = qkv + baseq + 2 * Dm;
    size_t basep = (size_t)b * Ns * Dm + (size_t)h * HDh;  // pre_proj layout

    for (int idx = tid; idx < Ns * 16; idx += 256) {
        int r = idx >> 4, f = idx & 15;
        *(float4*)(Ks + r * KV_PITCH + f * 4) = *(const float4*)(kp + (size_t)r * QKVS + f * 4);
        *(float4*)(Vs + r * KV_PITCH + f * 4) = *(const float4*)(vp + (size_t)r * QKVS + f * 4);
    }
    __syncthreads();

    size_t awbase = (size_t)bh * Ns * Ns;

    for (int qi = warp; qi < Ns; qi += 8) {
        Qr[warp * 64 + lane]      = qp[(size_t)qi * QKVS + lane];
        Qr[warp * 64 + lane + 32] = qp[(size_t)qi * QKVS + lane + 32];
        __syncwarp();

        const float4* Q4 = (const float4*)(Qr + warp * 64);
        float mx = -1e30f;
        for (int kk = lane; kk < Ns; kk += 32) {
            const float4* K4 = (const float4*)(Ks + kk * KV_PITCH);
            float dot = 0.f;
            #pragma unroll
            for (int d4 = 0; d4 < 16; d4++) {
                float4 qv = Q4[d4], kv = K4[d4];
                dot += qv.x * kv.x + qv.y * kv.y + qv.z * kv.z + qv.w * kv.w;
            }
            Sc[warp * SC_PITCH + kk] = dot;
            mx = fmaxf(mx, dot);
        }
        #pragma unroll
        for (int o = 16; o > 0; o >>= 1)
            mx = fmaxf(mx, __shfl_xor_sync(0xffffffffu, mx, o));

        float sum = 0.f;
        for (int kk = lane; kk < Ns; kk += 32) {
            float e = __expf(Sc[warp * SC_PITCH + kk] - mx);
            Sc[warp * SC_PITCH + kk] = e;
            sum += e;
        }
        #pragma unroll
        for (int o = 16; o > 0; o >>= 1)
            sum += __shfl_xor_sync(0xffffffffu, sum, o);
        float inv = 1.0f / sum;

        for (int kk = lane; kk < Ns; kk += 32) {
            float p = Sc[warp * SC_PITCH + kk] * inv;
            Sc[warp * SC_PITCH + kk] = p;
            attn_w[awbase + (size_t)qi * Ns + kk] = p;
        }
        __syncwarp();

        float2 acc = make_float2(0.f, 0.f);
        const float* ScW = Sc + warp * SC_PITCH;
        const float* Vp = Vs + lane * 2;
        for (int kk = 0; kk < Ns; kk++) {
            float p = ScW[kk];
            float2 vv = *(const float2*)(Vp + kk * KV_PITCH);
            acc.x += p * vv.x;
            acc.y += p * vv.y;
        }
        *(float2*)(pre_proj + basep + (size_t)qi * Dm + lane * 2) = acc;
        *(__half2*)(pp_h + basep + (size_t)qi * Dm + lane * 2) = __floats2half2_rn(acc.x, acc.y);
        __syncwarp();
    }
}

// ---------------------------------------------------------------------------
// Launch
// ---------------------------------------------------------------------------
extern "C" void kernel_launch(void* const* d_in, const int* in_sizes, int n_in,
                              void* d_out, int out_size) {
    const float* x     = (const float*)d_in[0];
    const float* ln1_g = (const float*)d_in[1];
    const float* ln1_b = (const float*)d_in[2];
    const float* wq    = (const float*)d_in[3];
    const float* bq    = (const float*)d_in[4];
    const float* wk    = (const float*)d_in[5];
    const float* bk    = (const float*)d_in[6];
    const float* wv    = (const float*)d_in[7];
    const float* bv    = (const float*)d_in[8];
    const float* wo    = (const float*)d_in[9];
    const float* bo    = (const float*)d_in[10];
    const float* ln2_g = (const float*)d_in[11];
    const float* ln2_b = (const float*)d_in[12];
    const float* w1    = (const float*)d_in[13];
    const float* b1    = (const float*)d_in[14];
    const float* w2    = (const float*)d_in[15];
    const float* b2    = (const float*)d_in[16];

    float* out = (float*)d_out;
    const size_t S = (size_t)Mrows * Dm;
    float* pre_proj = out;
    float* hidden   = out + S;
    float* attn_w   = out + 2 * S;

    __half *h_h, *pp_h, *ffn_h, *wqkvT, *woT, *w1T, *w2T;
    float *qkv, *hs, *bqkv;
    cudaGetSymbolAddress((void**)&h_h,   g_h_h);
    cudaGetSymbolAddress((void**)&qkv,   g_qkv);
    cudaGetSymbolAddress((void**)&pp_h,  g_pp_h);
    cudaGetSymbolAddress((void**)&hs,    g_hs);
    cudaGetSymbolAddress((void**)&ffn_h, g_ffn_h);
    cudaGetSymbolAddress((void**)&wqkvT, g_wqkvT);
    cudaGetSymbolAddress((void**)&woT,   g_woT);
    cudaGetSymbolAddress((void**)&w1T,   g_w1T);
    cudaGetSymbolAddress((void**)&w2T,   g_w2T);
    cudaGetSymbolAddress((void**)&bqkv,  g_bqkv);

    cudaFuncSetAttribute(attn_kernel, cudaFuncAttributeMaxDynamicSharedMemorySize, ATTN_SMEM_BYTES);

    // 0) weights -> transposed half [N,K]; fold q scale into wq/bq
    dim3 tb(32, 8);
    transpose_half_kernel<<<dim3(Dm / 32, Dm / 32), tb>>>(wq, wqkvT,            Dm, Dm, 0.125f);
    transpose_half_kernel<<<dim3(Dm / 32, Dm / 32), tb>>>(wk, wqkvT + Dm * Dm,  Dm, Dm, 1.0f);
    transpose_half_kernel<<<dim3(Dm / 32, Dm / 32), tb>>>(wv, wqkvT + 2*Dm*Dm,  Dm, Dm, 1.0f);
    transpose_half_kernel<<<dim3(Dm / 32, Dm / 32), tb>>>(wo, woT, Dm, Dm, 1.0f);
    transpose_half_kernel<<<dim3(DFFc / 32, Dm / 32), tb>>>(w1, w1T, Dm, DFFc, 1.0f);
    transpose_half_kernel<<<dim3(Dm / 32, DFFc / 32), tb>>>(w2, w2T, DFFc, Dm, 1.0f);
    bias_qkv_kernel<<<(QKVS + 255) / 256, 256>>>(bq, bk, bv, bqkv);

    // 1) h = LN1(x) (half)
    ln_kernel<<<Mrows, 256>>>(x, ln1_g, ln1_b, h_h);

    const int MT = (Mrows + 127) / 128;  // 99

    // 2) fused qkv projection: [M, 2304] fp32
    hgemm<false, false, false><<<dim3(QKVS / 128, MT), 256>>>(h_h, wqkvT, bqkv, nullptr, qkv, Mrows, QKVS, Dm);

    // 3) attention
    attn_kernel<<<Bsz * Hh, 256, ATTN_SMEM_BYTES>>>(qkv, attn_w, pre_proj, pp_h);

    // 4) hs = x + pre_proj @ wo + bo
    dim3 gD(Dm / 128, MT);
    hgemm<true, false, false><<<gD, 256>>>(pp_h, woT, bo, x, hs, Mrows, Dm, Dm);

    // 5) h = LN2(hs) (half)
    ln_kernel<<<Mrows, 256>>>(hs, ln2_g, ln2_b, h_h);

    // 6) ffn = gelu(h @ w1 + b1) (half)
    dim3 gF(DFFc / 128, MT);
    hgemm<false, true, true><<<gF, 256>>>(h_h, w1T, b1, nullptr, ffn_h, Mrows, DFFc, Dm);

    // 7) hidden = hs + ffn @ w2 + b2
    hgemm<true, false, false><<<gD, 256>>>(ffn_h, w2T, b2, hs, hidden, Mrows, Dm, DFFc);
}

// round 7
// speedup vs baseline: 4.0861x; 1.2696x over previous
#include <cuda_runtime.h>
#include <cuda_fp16.h>
#include <math.h>
#include <stddef.h>
#include <stdint.h>

// Problem constants
#define Bsz 64
#define Ns  197
#define Dm  768
#define Hh  12
#define HDh 64
#define DFFc 3072
#define Mrows (Bsz*Ns)          // 12608
#define QKVS 2304               // fused qkv row stride

// ---------------------------------------------------------------------------
// Scratch (device globals: no allocations allowed)
// ---------------------------------------------------------------------------
__device__ __half g_h_h  [Mrows*Dm];
__device__ float  g_qkv  [(size_t)Mrows*QKVS];
__device__ __half g_pp_h [Mrows*Dm];
__device__ float  g_hs   [Mrows*Dm];
__device__ __half g_ffn_h[(size_t)Mrows*DFFc];
__device__ __half g_wqkvT[QKVS*Dm];             // rows: wq*0.125 | wk | wv
__device__ __half g_woT  [Dm*Dm];
__device__ __half g_w1T  [DFFc*Dm];
__device__ __half g_w2T  [Dm*DFFc];
__device__ float  g_bqkv [QKVS];

// ---------------------------------------------------------------------------
// PTX helpers
// ---------------------------------------------------------------------------
__device__ __forceinline__ uint32_t smem_u32(const void* p) {
    uint32_t a;
    asm("{ .reg .u64 t; cvta.to.shared.u64 t, %1; cvt.u32.u64 %0, t; }" : "=r"(a) : "l"(p));
    return a;
}
__device__ __forceinline__ void cp16(uint32_t saddr, const void* g) {
    asm volatile("cp.async.cg.shared.global [%0], [%1], 16;" :: "r"(saddr), "l"(g));
}
#define CP_COMMIT() asm volatile("cp.async.commit_group;" ::: "memory")
#define CP_WAIT1()  asm volatile("cp.async.wait_group 1;" ::: "memory")

__device__ __forceinline__ void ldsm4(uint32_t& r0, uint32_t& r1, uint32_t& r2, uint32_t& r3,
                                      uint32_t a) {
    asm volatile("ldmatrix.sync.aligned.m8n8.x4.shared.b16 {%0,%1,%2,%3}, [%4];"
                 : "=r"(r0), "=r"(r1), "=r"(r2), "=r"(r3) : "r"(a));
}
__device__ __forceinline__ void mma_f16(float* d, const uint32_t* a,
                                        uint32_t b0, uint32_t b1) {
    asm volatile(
        "mma.sync.aligned.m16n8k16.row.col.f32.f16.f16.f32 "
        "{%0,%1,%2,%3}, {%4,%5,%6,%7}, {%8,%9}, {%0,%1,%2,%3};"
        : "+f"(d[0]), "+f"(d[1]), "+f"(d[2]), "+f"(d[3])
        : "r"(a[0]), "r"(a[1]), "r"(a[2]), "r"(a[3]), "r"(b0), "r"(b1));
}

// ---------------------------------------------------------------------------
// HGEMM: C = act(A @ Bt^T + bias [+ R]); A [M,K] half, Bt [N,K] half.
// Tile 128x128, BK=32, 3-stage cp.async, ldmatrix fragments.
// 8 warps 4(m) x 2(n), warp tile 32x64. Pitch 40 halves (80B).
// ---------------------------------------------------------------------------
#define STG_BYTES   20480           // (128*40)*2B per matrix, A+B
#define HG_SMEM     (3*STG_BYTES)   // 61440

template<bool RESID, bool GELU, bool OUTH>
__global__ __launch_bounds__(256)
void hgemm(const __half* __restrict__ A, const __half* __restrict__ Bt,
           const float* __restrict__ bias, const float* __restrict__ R,
           void* __restrict__ Cout, int M, int N, int K)
{
    extern __shared__ __align__(16) char smem[];
    const uint32_t sb = smem_u32(smem);

    const int tid = threadIdx.x;
    const int w = tid >> 5, lane = tid & 31;
    const int g = lane >> 2, tq = lane & 3;
    const int wm = w & 3, wn = w >> 2;
    const int row0 = blockIdx.y * 128, col0 = blockIdx.x * 128;

    // cp.async staging: thread -> (row = tid>>2 [+64], seg = tid&3), 16B each
    const int srow = tid >> 2, sseg = tid & 3;
    int ga0 = row0 + srow;      if (ga0 >= M) ga0 = M - 1;
    int ga1 = row0 + srow + 64; if (ga1 >= M) ga1 = M - 1;
    const __half* pA0 = A + (size_t)ga0 * K + sseg * 8;
    const __half* pA1 = A + (size_t)ga1 * K + sseg * 8;
    const __half* pB0 = Bt + (size_t)(col0 + srow) * K + sseg * 8;
    const __half* pB1 = Bt + (size_t)(col0 + srow + 64) * K + sseg * 8;
    const uint32_t stA0 = (uint32_t)(srow * 80 + sseg * 16);
    const uint32_t stA1 = (uint32_t)((srow + 64) * 80 + sseg * 16);

    float acc[2][8][4];
    #pragma unroll
    for (int mt = 0; mt < 2; mt++)
        #pragma unroll
        for (int nt = 0; nt < 8; nt++)
            #pragma unroll
            for (int i = 0; i < 4; i++) acc[mt][nt][i] = 0.f;

    const int KC = K >> 5;   // chunks of 32

    // ldmatrix base offsets (within a stage)
    //  A: row = wm*32 + mt*16 + (lane&15), seg = ks*2 + (lane>>4)
    const uint32_t aRow = (uint32_t)(wm * 32 + (lane & 15));
    const uint32_t aSegL = (uint32_t)(lane >> 4);
    //  B: row = wn*64 + bt*16 + (lane&7) + ((lane>>4)<<3), seg = ks*2 + ((lane>>3)&1)
    const uint32_t bRow = (uint32_t)(wn * 64 + (lane & 7) + ((lane >> 4) << 3));
    const uint32_t bSegL = (uint32_t)((lane >> 3) & 1);

    #define ISSUE(s, ck) do { \
        const uint32_t so = sb + (uint32_t)(s) * STG_BYTES; \
        const int kt = (ck) * 32; \
        cp16(so + stA0, pA0 + kt); \
        cp16(so + stA1, pA1 + kt); \
        cp16(so + 10240 + stA0, pB0 + kt); \
        cp16(so + 10240 + stA1, pB1 + kt); \
    } while (0)

    ISSUE(0, 0); CP_COMMIT();
    ISSUE(1, 1); CP_COMMIT();

    int s = 0;
    for (int ck = 0; ck < KC; ck++) {
        CP_WAIT1();
        __syncthreads();
        const uint32_t so = sb + (uint32_t)s * STG_BYTES;

        #pragma unroll
        for (int ks = 0; ks < 2; ks++) {
            uint32_t afr[2][4];
            #pragma unroll
            for (int mt = 0; mt < 2; mt++) {
                uint32_t addr = so + (aRow + mt * 16) * 80 + (ks * 2 + aSegL) * 16;
                ldsm4(afr[mt][0], afr[mt][1], afr[mt][2], afr[mt][3], addr);
            }
            uint32_t bfr[4][4];
            #pragma unroll
            for (int bt = 0; bt < 4; bt++) {
                uint32_t addr = so + 10240 + (bRow + bt * 16) * 80 + (ks * 2 + bSegL) * 16;
                ldsm4(bfr[bt][0], bfr[bt][1], bfr[bt][2], bfr[bt][3], addr);
            }
            #pragma unroll
            for (int nt = 0; nt < 8; nt++) {
                uint32_t b0 = bfr[nt >> 1][(nt & 1) * 2];
                uint32_t b1 = bfr[nt >> 1][(nt & 1) * 2 + 1];
                mma_f16(acc[0][nt], afr[0], b0, b1);
                mma_f16(acc[1][nt], afr[1], b0, b1);
            }
        }
        if (ck + 2 < KC) ISSUE((s + 2) % 3, ck + 2);
        CP_COMMIT();
        s = (s + 1) % 3;
    }
    #undef ISSUE

    // Epilogue: thread owns rows g/g+8, cols 2tq..2tq+1 per mma tile
    #pragma unroll
    for (int mt = 0; mt < 2; mt++) {
        #pragma unroll
        for (int nt = 0; nt < 8; nt++) {
            const int cc = col0 + wn * 64 + nt * 8 + 2 * tq;
            const float b0 = bias[cc], b1 = bias[cc + 1];
            #pragma unroll
            for (int half_ = 0; half_ < 2; half_++) {
                const int r_ = row0 + wm * 32 + mt * 16 + g + half_ * 8;
                if (r_ < M) {
                    float v0 = acc[mt][nt][half_ * 2 + 0] + b0;
                    float v1 = acc[mt][nt][half_ * 2 + 1] + b1;
                    if (RESID) {
                        const float* rp = R + (size_t)r_ * N + cc;
                        v0 += rp[0]; v1 += rp[1];
                    }
                    if (GELU) {
                        v0 = 0.5f * v0 * (1.0f + erff(v0 * 0.70710678118654752f));
                        v1 = 0.5f * v1 * (1.0f + erff(v1 * 0.70710678118654752f));
                    }
                    if (OUTH) {
                        *(__half2*)((__half*)Cout + (size_t)r_ * N + cc) =
                            __floats2half2_rn(v0, v1);
                    } else {
                        *(float2*)((float*)Cout + (size_t)r_ * N + cc) =
                            make_float2(v0, v1);
                    }
                }
            }
        }
    }
}

// ---------------------------------------------------------------------------
// Transpose + convert to half (+scale)
// ---------------------------------------------------------------------------
__global__ void transpose_half_kernel(const float* __restrict__ in,
                                      __half* __restrict__ out,
                                      int rows, int cols, float scale) {
    __shared__ float t[32][33];
    int bx = blockIdx.x * 32, by = blockIdx.y * 32;
    int x = bx + threadIdx.x, y = by + threadIdx.y;
    #pragma unroll
    for (int i = 0; i < 32; i += 8)
        t[threadIdx.y + i][threadIdx.x] = in[(size_t)(y + i) * cols + x];
    __syncthreads();
    x = by + threadIdx.x; y = bx + threadIdx.y;
    #pragma unroll
    for (int i = 0; i < 32; i += 8)
        out[(size_t)(y + i) * rows + x] = __float2half(t[threadIdx.x][threadIdx.y + i] * scale);
}

__global__ void bias_qkv_kernel(const float* __restrict__ bq,
                                const float* __restrict__ bk,
                                const float* __restrict__ bv,
                                float* __restrict__ out) {
    int i = blockIdx.x * 256 + threadIdx.x;
    if (i < Dm)            out[i] = bq[i] * 0.125f;
    else if (i < 2 * Dm)   out[i] = bk[i - Dm];
    else if (i < 3 * Dm)   out[i] = bv[i - 2 * Dm];
}

// ---------------------------------------------------------------------------
// LayerNorm -> half output
// ---------------------------------------------------------------------------
__global__ void ln_kernel(const float* __restrict__ x,
                          const float* __restrict__ g,
                          const float* __restrict__ b,
                          __half* __restrict__ out) {
    int row = blockIdx.x;
    const float* xr = x + (size_t)row * Dm;
    float s = 0.f, s2 = 0.f;
    for (int i = threadIdx.x; i < Dm; i += 256) {
        float v = xr[i];
        s += v; s2 += v * v;
    }
    __shared__ float r1[256], r2[256];
    r1[threadIdx.x] = s; r2[threadIdx.x] = s2;
    __syncthreads();
    #pragma unroll
    for (int o = 128; o > 0; o >>= 1) {
        if (threadIdx.x < o) {
            r1[threadIdx.x] += r1[threadIdx.x + o];
            r2[threadIdx.x] += r2[threadIdx.x + o];
        }
        __syncthreads();
    }
    float mu  = r1[0] * (1.0f / Dm);
    float var = r2[0] * (1.0f / Dm) - mu * mu;
    float inv = rsqrtf(var + 1e-5f);
    __half* orow = out + (size_t)row * Dm;
    for (int i = threadIdx.x; i < Dm; i += 256)
        orow[i] = __float2half((xr[i] - mu) * inv * g[i] + b[i]);
}

// ---------------------------------------------------------------------------
// Attention: one CTA per (b, h). q/k/v from fused fp32 buffer (stride QKVS).
// ---------------------------------------------------------------------------
#define KV_PITCH 68
#define SC_PITCH 200
#define ATTN_SMEM_FLOATS (Ns*KV_PITCH*2 + 8*64 + 8*SC_PITCH)
#define ATTN_SMEM_BYTES  (ATTN_SMEM_FLOATS * 4)

__global__ void attn_kernel(const float* __restrict__ qkv,
                            float* __restrict__ attn_w,
                            float* __restrict__ pre_proj,
                            __half* __restrict__ pp_h) {
    extern __shared__ float sm[];
    float* Ks = sm;
    float* Vs = Ks + Ns * KV_PITCH;
    float* Qr = Vs + Ns * KV_PITCH;
    float* Sc = Qr + 8 * 64;

    int bh = blockIdx.x;
    int b = bh / Hh, h = bh % Hh;
    int tid = threadIdx.x, lane = tid & 31, warp = tid >> 5;

    size_t baseq = (size_t)b * Ns * QKVS + (size_t)h * HDh;
    const float* qp = qkv + baseq;
    const float* kp = qkv + baseq + Dm;
    const float* vp = qkv + baseq + 2 * Dm;
    size_t basep = (size_t)b * Ns * Dm + (size_t)h * HDh;

    for (int idx = tid; idx < Ns * 16; idx += 256) {
        int r = idx >> 4, f = idx & 15;
        *(float4*)(Ks + r * KV_PITCH + f * 4) = *(const float4*)(kp + (size_t)r * QKVS + f * 4);
        *(float4*)(Vs + r * KV_PITCH + f * 4) = *(const float4*)(vp + (size_t)r * QKVS + f * 4);
    }
    __syncthreads();

    size_t awbase = (size_t)bh * Ns * Ns;

    for (int qi = warp; qi < Ns; qi += 8) {
        Qr[warp * 64 + lane]      = qp[(size_t)qi * QKVS + lane];
        Qr[warp * 64 + lane + 32] = qp[(size_t)qi * QKVS + lane + 32];
        __syncwarp();

        const float4* Q4 = (const float4*)(Qr + warp * 64);
        float mx = -1e30f;
        for (int kk = lane; kk < Ns; kk += 32) {
            const float4* K4 = (const float4*)(Ks + kk * KV_PITCH);
            float dot = 0.f;
            #pragma unroll
            for (int d4 = 0; d4 < 16; d4++) {
                float4 qv = Q4[d4], kv = K4[d4];
                dot += qv.x * kv.x + qv.y * kv.y + qv.z * kv.z + qv.w * kv.w;
            }
            Sc[warp * SC_PITCH + kk] = dot;
            mx = fmaxf(mx, dot);
        }
        #pragma unroll
        for (int o = 16; o > 0; o >>= 1)
            mx = fmaxf(mx, __shfl_xor_sync(0xffffffffu, mx, o));

        float sum = 0.f;
        for (int kk = lane; kk < Ns; kk += 32) {
            float e = __expf(Sc[warp * SC_PITCH + kk] - mx);
            Sc[warp * SC_PITCH + kk] = e;
            sum += e;
        }
        #pragma unroll
        for (int o = 16; o > 0; o >>= 1)
            sum += __shfl_xor_sync(0xffffffffu, sum, o);
        float inv = 1.0f / sum;

        for (int kk = lane; kk < Ns; kk += 32) {
            float p = Sc[warp * SC_PITCH + kk] * inv;
            Sc[warp * SC_PITCH + kk] = p;
            attn_w[awbase + (size_t)qi * Ns + kk] = p;
        }
        __syncwarp();

        float2 acc = make_float2(0.f, 0.f);
        const float* ScW = Sc + warp * SC_PITCH;
        const float* Vp = Vs + lane * 2;
        for (int kk = 0; kk < Ns; kk++) {
            float p = ScW[kk];
            float2 vv = *(const float2*)(Vp + kk * KV_PITCH);
            acc.x += p * vv.x;
            acc.y += p * vv.y;
        }
        *(float2*)(pre_proj + basep + (size_t)qi * Dm + lane * 2) = acc;
        *(__half2*)(pp_h + basep + (size_t)qi * Dm + lane * 2) = __floats2half2_rn(acc.x, acc.y);
        __syncwarp();
    }
}

// ---------------------------------------------------------------------------
// Launch
// ---------------------------------------------------------------------------
extern "C" void kernel_launch(void* const* d_in, const int* in_sizes, int n_in,
                              void* d_out, int out_size) {
    const float* x     = (const float*)d_in[0];
    const float* ln1_g = (const float*)d_in[1];
    const float* ln1_b = (const float*)d_in[2];
    const float* wq    = (const float*)d_in[3];
    const float* bq    = (const float*)d_in[4];
    const float* wk    = (const float*)d_in[5];
    const float* bk    = (const float*)d_in[6];
    const float* wv    = (const float*)d_in[7];
    const float* bv    = (const float*)d_in[8];
    const float* wo    = (const float*)d_in[9];
    const float* bo    = (const float*)d_in[10];
    const float* ln2_g = (const float*)d_in[11];
    const float* ln2_b = (const float*)d_in[12];
    const float* w1    = (const float*)d_in[13];
    const float* b1    = (const float*)d_in[14];
    const float* w2    = (const float*)d_in[15];
    const float* b2    = (const float*)d_in[16];

    float* out = (float*)d_out;
    const size_t S = (size_t)Mrows * Dm;
    float* pre_proj = out;
    float* hidden   = out + S;
    float* attn_w   = out + 2 * S;

    __half *h_h, *pp_h, *ffn_h, *wqkvT, *woT, *w1T, *w2T;
    float *qkv, *hs, *bqkv;
    cudaGetSymbolAddress((void**)&h_h,   g_h_h);
    cudaGetSymbolAddress((void**)&qkv,   g_qkv);
    cudaGetSymbolAddress((void**)&pp_h,  g_pp_h);
    cudaGetSymbolAddress((void**)&hs,    g_hs);
    cudaGetSymbolAddress((void**)&ffn_h, g_ffn_h);
    cudaGetSymbolAddress((void**)&wqkvT, g_wqkvT);
    cudaGetSymbolAddress((void**)&woT,   g_woT);
    cudaGetSymbolAddress((void**)&w1T,   g_w1T);
    cudaGetSymbolAddress((void**)&w2T,   g_w2T);
    cudaGetSymbolAddress((void**)&bqkv,  g_bqkv);

    cudaFuncSetAttribute(attn_kernel, cudaFuncAttributeMaxDynamicSharedMemorySize, ATTN_SMEM_BYTES);
    cudaFuncSetAttribute(hgemm<false, false, false>, cudaFuncAttributeMaxDynamicSharedMemorySize, HG_SMEM);
    cudaFuncSetAttribute(hgemm<true, false, false>,  cudaFuncAttributeMaxDynamicSharedMemorySize, HG_SMEM);
    cudaFuncSetAttribute(hgemm<false, true, true>,   cudaFuncAttributeMaxDynamicSharedMemorySize, HG_SMEM);

    // 0) weights -> transposed half [N,K]; fold q scale into wq/bq
    dim3 tb(32, 8);
    transpose_half_kernel<<<dim3(Dm / 32, Dm / 32), tb>>>(wq, wqkvT,           Dm, Dm, 0.125f);
    transpose_half_kernel<<<dim3(Dm / 32, Dm / 32), tb>>>(wk, wqkvT + Dm * Dm, Dm, Dm, 1.0f);
    transpose_half_kernel<<<dim3(Dm / 32, Dm / 32), tb>>>(wv, wqkvT + 2*Dm*Dm, Dm, Dm, 1.0f);
    transpose_half_kernel<<<dim3(Dm / 32, Dm / 32), tb>>>(wo, woT, Dm, Dm, 1.0f);
    transpose_half_kernel<<<dim3(DFFc / 32, Dm / 32), tb>>>(w1, w1T, Dm, DFFc, 1.0f);
    transpose_half_kernel<<<dim3(Dm / 32, DFFc / 32), tb>>>(w2, w2T, DFFc, Dm, 1.0f);
    bias_qkv_kernel<<<(QKVS + 255) / 256, 256>>>(bq, bk, bv, bqkv);

    // 1) h = LN1(x) (half)
    ln_kernel<<<Mrows, 256>>>(x, ln1_g, ln1_b, h_h);

    const int MT = (Mrows + 127) / 128;  // 99

    // 2) fused qkv projection: [M, 2304] fp32
    hgemm<false, false, false><<<dim3(QKVS / 128, MT), 256, HG_SMEM>>>(
        h_h, wqkvT, bqkv, nullptr, qkv, Mrows, QKVS, Dm);

    // 3) attention
    attn_kernel<<<Bsz * Hh, 256, ATTN_SMEM_BYTES>>>(qkv, attn_w, pre_proj, pp_h);

    // 4) hs = x + pre_proj @ wo + bo
    dim3 gD(Dm / 128, MT);
    hgemm<true, false, false><<<gD, 256, HG_SMEM>>>(pp_h, woT, bo, x, hs, Mrows, Dm, Dm);

    // 5) h = LN2(hs) (half)
    ln_kernel<<<Mrows, 256>>>(hs, ln2_g, ln2_b, h_h);

    // 6) ffn = gelu(h @ w1 + b1) (half)
    dim3 gF(DFFc / 128, MT);
    hgemm<false, true, true><<<gF, 256, HG_SMEM>>>(h_h, w1T, b1, nullptr, ffn_h, Mrows, DFFc, Dm);

    // 7) hidden = hs + ffn @ w2 + b2
    hgemm<true, false, false><<<gD, 256, HG_SMEM>>>(ffn_h, w2T, b2, hs, hidden, Mrows, Dm, DFFc);
}